// round 2
// baseline (speedup 1.0000x reference)
#include <cuda_runtime.h>
#include <cstdint>
#include <math.h>

// ---------------- problem constants ----------------
#define VOCAB 30522
#define BB 2
#define SS 512
#define DD 768
#define JJ 12
#define KNB 4
#define TT (BB*SS)        // 2048 tokens
#define K_MLP (13*DD)     // 9984
#define N_MLP (JJ*DD)     // 9216
#define K_ATT (2*DD)      // 1536
#define NUM_LABELS 7

// ---------------- scratch (__device__ globals; allocation-free) ----------------
__device__ int   d_last0[VOCAB];
__device__ int   d_last1[VOCAB];
__device__ float d_rij[(size_t)TT * K_MLP];     // [2048, 9984]  (seq | n_flat)
__device__ float d_c[(size_t)TT * N_MLP];       // [2048, 9216]  gated neighbors
__device__ float d_comb[(size_t)TT * K_ATT];    // [2048, 1536]  (mix | seq)
__device__ float d_attnout[(size_t)TT * DD];    // [2048, 768]

// ---------------- small kernels ----------------
__global__ void k_init_last() {
    int i = blockIdx.x * blockDim.x + threadIdx.x;
    if (i < VOCAB) { d_last0[i] = -1; d_last1[i] = -1; }
}

__global__ void k_scatter(const int* __restrict__ ids) {
    int s = blockIdx.x * blockDim.x + threadIdx.x;   // 0..1023
    if (s < SS)            atomicMax(&d_last0[ids[s]], s);
    else if (s < 2 * SS)   atomicMax(&d_last1[ids[s]], s - SS);
}

// Build rij[t] = [ seq_t (768) | n_flat_t (9216) ], float4-vectorized.
// 192 threads: one float4 lane each (768/4 = 192).
__global__ void k_build_rij(const float* __restrict__ seqf, const int* __restrict__ nbr) {
    const float4* seq = (const float4*)seqf;
    int t = blockIdx.x;
    int b = t >> 9;                 // t / 512
    int tid = threadIdx.x;          // 192 threads
    const int D4 = DD / 4;          // 192
    __shared__ int rowidx[JJ * KNB];
    if (tid < JJ * KNB) {
        int id = nbr[t * (JJ * KNB) + tid];
        int r = -1;
        if (b == 0) {
            int p0 = d_last0[id];
            if (p0 >= 0) r = p0;                 // global token row in example 0
        } else {
            int p1 = d_last1[id];
            if (p1 >= 0) r = SS + p1;            // example 1 overwrites ex0
            else { int p0 = d_last0[id]; if (p0 >= 0) r = p0; }
        }
        rowidx[tid] = r;
    }
    __syncthreads();
    float4* out = (float4*)(d_rij + (size_t)t * K_MLP);
    const float4* myseq = seq + (size_t)t * D4;
    out[tid] = myseq[tid];
    #pragma unroll 1
    for (int j = 0; j < JJ; ++j) {
        int r0 = rowidx[j*4+0], r1 = rowidx[j*4+1], r2 = rowidx[j*4+2], r3 = rowidx[j*4+3];
        float4 a = make_float4(0.f, 0.f, 0.f, 0.f);
        if (r0 >= 0) { float4 v = seq[(size_t)r0 * D4 + tid]; a.x += v.x; a.y += v.y; a.z += v.z; a.w += v.w; }
        if (r1 >= 0) { float4 v = seq[(size_t)r1 * D4 + tid]; a.x += v.x; a.y += v.y; a.z += v.z; a.w += v.w; }
        if (r2 >= 0) { float4 v = seq[(size_t)r2 * D4 + tid]; a.x += v.x; a.y += v.y; a.z += v.z; a.w += v.w; }
        if (r3 >= 0) { float4 v = seq[(size_t)r3 * D4 + tid]; a.x += v.x; a.y += v.y; a.z += v.z; a.w += v.w; }
        out[D4 + j * D4 + tid] = a;
    }
}

// ---------------- tf32 mma.sync GEMM: C[M,N] = A[M,K] @ B[N,K]^T (+epilogue) ----------------
#define BM 128
#define BN 128
#define BKK 32
#define ASTRIDE 36                         // 32 + pad(4) -> conflict-free frag loads
#define SMEM_FLOATS (2 * (BM * ASTRIDE + BN * ASTRIDE))
#define SMEM_BYTES (SMEM_FLOATS * 4)       // 73728 B

__device__ __forceinline__ void cp_async16(void* sdst, const void* gsrc) {
    unsigned s = (unsigned)__cvta_generic_to_shared(sdst);
    asm volatile("cp.async.cg.shared.global [%0], [%1], 16;" :: "r"(s), "l"(gsrc));
}
__device__ __forceinline__ void cp_commit() { asm volatile("cp.async.commit_group;"); }
template<int N> __device__ __forceinline__ void cp_wait() {
    asm volatile("cp.async.wait_group %0;" :: "n"(N));
}
__device__ __forceinline__ unsigned f2tf(float x) {
    unsigned r; asm("cvt.rna.tf32.f32 %0, %1;" : "=r"(r) : "f"(x)); return r;
}
__device__ __forceinline__ void mma8(float* c, const unsigned* a, const unsigned* b) {
    asm volatile("mma.sync.aligned.m16n8k8.row.col.f32.tf32.tf32.f32 "
                 "{%0,%1,%2,%3}, {%4,%5,%6,%7}, {%8,%9}, {%0,%1,%2,%3};"
                 : "+f"(c[0]), "+f"(c[1]), "+f"(c[2]), "+f"(c[3])
                 : "r"(a[0]), "r"(a[1]), "r"(a[2]), "r"(a[3]), "r"(b[0]), "r"(b[1]));
}

// EPI==0: Cg = sigmoid(acc + bias[n]) * Ag[m][768+n]   (gated MLP, writes d_c)
// EPI==1: Cg = tanh(acc + bias[n])                      (attention projection)
template<int EPI>
__global__ void __launch_bounds__(256, 2)
k_gemm(const float* __restrict__ Ag, const float* __restrict__ Bg,
       const float* __restrict__ bias, float* __restrict__ Cg,
       int Ndim, int Kdim)
{
    extern __shared__ float sm[];
    float* As = sm;                          // [2][BM][ASTRIDE]
    float* Bs = sm + 2 * BM * ASTRIDE;       // [2][BN][ASTRIDE]

    const int bm = blockIdx.y * BM;
    const int bn = blockIdx.x * BN;
    const int tid  = threadIdx.x;
    const int warp = tid >> 5, lane = tid & 31;
    const int wm = warp >> 2, wn = warp & 3;     // 2x4 warp grid, 64x32 per warp
    const int g  = lane >> 2, tg = lane & 3;

    const int lrow = tid >> 3;                   // 0..31
    const int lcol = (tid & 7) * 4;              // 0..28
    const float* Aload = Ag + (size_t)(bm + lrow) * Kdim + lcol;
    const float* Bload = Bg + (size_t)(bn + lrow) * Kdim + lcol;

    float acc[4][4][4];
    #pragma unroll
    for (int i = 0; i < 4; ++i)
        #pragma unroll
        for (int j = 0; j < 4; ++j)
            #pragma unroll
            for (int r = 0; r < 4; ++r) acc[i][j][r] = 0.f;

    auto stage = [&](int buf, int k0) {
        float* a = As + buf * BM * ASTRIDE;
        float* b = Bs + buf * BN * ASTRIDE;
        #pragma unroll
        for (int r = 0; r < 4; ++r) {
            cp_async16(a + (lrow + r * 32) * ASTRIDE + lcol, Aload + (size_t)r * 32 * Kdim + k0);
            cp_async16(b + (lrow + r * 32) * ASTRIDE + lcol, Bload + (size_t)r * 32 * Kdim + k0);
        }
        cp_commit();
    };

    const int nk = Kdim / BKK;
    stage(0, 0);
    for (int kt = 0; kt < nk; ++kt) {
        const int buf = kt & 1;
        if (kt + 1 < nk) { stage(buf ^ 1, (kt + 1) * BKK); cp_wait<1>(); }
        else             { cp_wait<0>(); }
        __syncthreads();
        const float* a = As + buf * BM * ASTRIDE;
        const float* b = Bs + buf * BN * ASTRIDE;
        #pragma unroll
        for (int kk = 0; kk < 4; ++kk) {
            const int kb = kk * 8;
            unsigned afr[4][4], bfr[4][2];
            #pragma unroll
            for (int i = 0; i < 4; ++i) {
                const float* ap = a + (wm * 64 + i * 16 + g) * ASTRIDE + kb + tg;
                afr[i][0] = f2tf(ap[0]);
                afr[i][1] = f2tf(ap[8 * ASTRIDE]);
                afr[i][2] = f2tf(ap[4]);
                afr[i][3] = f2tf(ap[8 * ASTRIDE + 4]);
            }
            #pragma unroll
            for (int j = 0; j < 4; ++j) {
                const float* bp = b + (wn * 32 + j * 8 + g) * ASTRIDE + kb + tg;
                bfr[j][0] = f2tf(bp[0]);
                bfr[j][1] = f2tf(bp[4]);
            }
            #pragma unroll
            for (int i = 0; i < 4; ++i)
                #pragma unroll
                for (int j = 0; j < 4; ++j)
                    mma8(acc[i][j], afr[i], bfr[j]);
        }
        __syncthreads();
    }

    // epilogue
    #pragma unroll
    for (int i = 0; i < 4; ++i) {
        #pragma unroll
        for (int j = 0; j < 4; ++j) {
            #pragma unroll
            for (int r = 0; r < 4; ++r) {
                int m = bm + wm * 64 + i * 16 + g + ((r >> 1) << 3);
                int n = bn + wn * 32 + j * 8 + tg * 2 + (r & 1);
                float v = acc[i][j][r] + bias[n];
                if (EPI == 0) {
                    float nf = Ag[(size_t)m * Kdim + DD + n];
                    Cg[(size_t)m * Ndim + n] = nf / (1.f + __expf(-v));
                } else {
                    Cg[(size_t)m * Ndim + n] = tanhf(v);
                }
            }
        }
    }
}

// ---------------- per-token attention: scores -> softmax -> mix -> combined ----------------
__global__ void k_attn_mix(const float* __restrict__ seq) {
    int t = blockIdx.x;
    int tid = threadIdx.x;              // 256
    __shared__ float s_seq[DD];
    __shared__ float s_scores[JJ];
    const float* c = d_c + (size_t)t * N_MLP;
    for (int d = tid; d < DD; d += 256) s_seq[d] = seq[(size_t)t * DD + d];
    __syncthreads();
    int warp = tid >> 5, lane = tid & 31;
    for (int j = warp; j < JJ; j += 8) {
        float p = 0.f;
        for (int d = lane; d < DD; d += 32) p += s_seq[d] * c[j * DD + d];
        #pragma unroll
        for (int o = 16; o > 0; o >>= 1) p += __shfl_xor_sync(0xFFFFFFFFu, p, o);
        if (lane == 0) s_scores[j] = p;
    }
    __syncthreads();
    float mx = -1e30f;
    #pragma unroll
    for (int j = 0; j < JJ; ++j) mx = fmaxf(mx, s_scores[j]);
    float e[JJ]; float sum = 0.f;
    #pragma unroll
    for (int j = 0; j < JJ; ++j) { e[j] = __expf(s_scores[j] - mx); sum += e[j]; }
    float inv = 1.f / sum;
    float* comb = d_comb + (size_t)t * K_ATT;
    for (int d = tid; d < DD; d += 256) {
        float m = 0.f;
        #pragma unroll
        for (int j = 0; j < JJ; ++j) m += e[j] * c[j * DD + d];
        comb[d]      = m * inv;      // mix
        comb[DD + d] = s_seq[d];     // sequence_output
    }
}

// ---------------- final logits: [seq | attn_out] @ W_cls^T + b_cls ----------------
__global__ void k_logits(const float* __restrict__ seq, const float* __restrict__ Wcls,
                         const float* __restrict__ bcls, float* __restrict__ out) {
    int t = blockIdx.x;
    int warp = threadIdx.x >> 5, lane = threadIdx.x & 31;   // 7 warps
    if (warp >= NUM_LABELS) return;
    const float* w = Wcls + (size_t)warp * K_ATT;
    const float* a = seq + (size_t)t * DD;
    const float* b = d_attnout + (size_t)t * DD;
    float p = 0.f;
    for (int f = lane; f < DD; f += 32) p += a[f] * w[f] + b[f] * w[DD + f];
    #pragma unroll
    for (int o = 16; o > 0; o >>= 1) p += __shfl_xor_sync(0xFFFFFFFFu, p, o);
    if (lane == 0) out[t * NUM_LABELS + warp] = p + bcls[warp];
}

// ---------------- launch ----------------
extern "C" void kernel_launch(void* const* d_in, const int* in_sizes, int n_in,
                              void* d_out, int out_size) {
    const float* seq  = (const float*)d_in[0];
    const int*   ids  = (const int*)d_in[1];
    const int*   nbr  = (const int*)d_in[2];
    const float* Wmlp = (const float*)d_in[3];
    const float* bmlp = (const float*)d_in[4];
    const float* Watt = (const float*)d_in[5];
    const float* batt = (const float*)d_in[6];
    const float* Wcls = (const float*)d_in[7];
    const float* bcls = (const float*)d_in[8];
    float* out = (float*)d_out;

    void *rij_p, *c_p, *comb_p, *att_p;
    cudaGetSymbolAddress(&rij_p,  d_rij);
    cudaGetSymbolAddress(&c_p,    d_c);
    cudaGetSymbolAddress(&comb_p, d_comb);
    cudaGetSymbolAddress(&att_p,  d_attnout);

    cudaFuncSetAttribute(k_gemm<0>, cudaFuncAttributeMaxDynamicSharedMemorySize, SMEM_BYTES);
    cudaFuncSetAttribute(k_gemm<1>, cudaFuncAttributeMaxDynamicSharedMemorySize, SMEM_BYTES);

    k_init_last<<<(VOCAB + 255) / 256, 256>>>();
    k_scatter<<<4, 256>>>(ids);
    k_build_rij<<<TT, 192>>>(seq, nbr);

    // gated MLP: c = sigmoid(rij @ Wmlp^T + b) * n_flat
    k_gemm<0><<<dim3(N_MLP / BN, TT / BM), 256, SMEM_BYTES>>>(
        (const float*)rij_p, Wmlp, bmlp, (float*)c_p, N_MLP, K_MLP);

    // attention mix + combined
    k_attn_mix<<<TT, 256>>>(seq);

    // attn_out = tanh(combined @ Watt^T + b)
    k_gemm<1><<<dim3(DD / BN, TT / BM), 256, SMEM_BYTES>>>(
        (const float*)comb_p, Watt, batt, (float*)att_p, DD, K_ATT);

    // logits
    k_logits<<<TT, 224>>>(seq, Wcls, bcls, out);
}